// round 15
// baseline (speedup 1.0000x reference)
#include <cuda_runtime.h>
#include <mma.h>
#include <math.h>
#include <stdint.h>

using namespace nvcuda;

#define SQ    4096
#define NH_   16
#define NKV_  2
#define HD_   128
#define HID_  2048
#define GRP_  8
// per-head causal-packed S scratch: sum_qb 128*(qb+1)*128 = 16384*528
#define STOT  8650752

// ---------------- scratch (device globals; no allocation allowed) ----------------
__device__ float g_q[SQ * NH_ * HD_];      // [s][h*128+d]   (tf32-rounded after rope)
__device__ float g_k[SQ * NKV_ * HD_];
__device__ float g_v[SQ * NKV_ * HD_];
__device__ float g_attn[SQ * NH_ * HD_];   // tf32-rounded at store
__device__ float g_m[NH_ * SQ];
__device__ float g_l[NH_ * SQ];
__device__ float g_colsum[NH_ * SQ];
__device__ float g_invfreq[64];
// tf32-pre-rounded operand copies
__device__ float g_hst[SQ * HID_];
__device__ float g_qwt[NH_ * HD_ * HID_];
__device__ float g_kwt[NKV_ * HD_ * HID_];
__device__ float g_vwt[NKV_ * HD_ * HID_];
__device__ float g_owt[HID_ * NH_ * HD_];
// materialized raw attention logits (pre-scale), causal-packed
__device__ float g_s[(size_t)NH_ * STOT];

__device__ __forceinline__ float t32(float x) { return wmma::__float_to_tf32(x); }

__device__ __forceinline__ void cp16(void* smem, const void* gmem)
{
    unsigned s = (unsigned)__cvta_generic_to_shared(smem);
    asm volatile("cp.async.cg.shared.global [%0], [%1], 16;\n" :: "r"(s), "l"(gmem));
}
#define CP_COMMIT()  asm volatile("cp.async.commit_group;\n")
#define CP_WAIT(n)   asm volatile("cp.async.wait_group %0;\n" :: "n"(n))

// ---------------- exact inv_freq table ----------------
__global__ void compute_invfreq()
{
    int j = threadIdx.x;
    if (j < 64) g_invfreq[j] = (float)(1.0 / pow(1.0e6, (double)j / 64.0));
}

// ---------------- pre-round to tf32 (vectorized) ----------------
__global__ void copy_round4(float* __restrict__ dst, const float* __restrict__ src, int n4)
{
    int i = blockIdx.x * blockDim.x + threadIdx.x;
    if (i >= n4) return;
    float4 v = ((const float4*)src)[i];
    v.x = t32(v.x); v.y = t32(v.y); v.z = t32(v.z); v.w = t32(v.w);
    ((float4*)dst)[i] = v;
}

// ---------------- pipelined TF32 NT GEMM core (round-13 proven config) ----------------
// BM=BN=128, BK=32, 2-stage cp.async, 256 threads, warp tile 64x32, 2 CTAs/SM
#define GEMM_SMEM_BYTES (4 * 128 * 36 * 4)
__device__ __forceinline__ void gemm_core(const float* __restrict__ Ag,
                                          const float* __restrict__ Bg,
                                          float* __restrict__ Cg,
                                          int K, int ldc)
{
    extern __shared__ float sm[];
    float* As = sm;                  // 2 x [128][36]
    float* Bs = sm + 2 * 128 * 36;
    const int tid  = threadIdx.x;
    const int warp = tid >> 5;
    const int wm = warp >> 2;        // 0..1
    const int wn = warp & 3;         // 0..3

    wmma::fragment<wmma::accumulator, 16, 16, 8, float> acc[4][2];
#pragma unroll
    for (int i = 0; i < 4; i++)
#pragma unroll
        for (int j = 0; j < 2; j++) wmma::fill_fragment(acc[i][j], 0.0f);

    const int nk = K >> 5;
    {
        float* Ad = As; float* Bd = Bs;
#pragma unroll
        for (int it = 0; it < 4; it++) {
            int fid = tid + it * 256;
            int r = fid >> 3, c = (fid & 7) * 4;
            cp16(&Ad[r*36 + c], &Ag[(size_t)r * K + c]);
            cp16(&Bd[r*36 + c], &Bg[(size_t)r * K + c]);
        }
        CP_COMMIT();
    }
    for (int t = 0; t < nk; t++) {
        if (t + 1 < nk) {
            int k0 = (t + 1) << 5;
            float* Ad = As + ((t+1)&1) * 128*36;
            float* Bd = Bs + ((t+1)&1) * 128*36;
#pragma unroll
            for (int it = 0; it < 4; it++) {
                int fid = tid + it * 256;
                int r = fid >> 3, c = (fid & 7) * 4;
                cp16(&Ad[r*36 + c], &Ag[(size_t)r * K + k0 + c]);
                cp16(&Bd[r*36 + c], &Bg[(size_t)r * K + k0 + c]);
            }
            CP_COMMIT();
            CP_WAIT(1);
        } else {
            CP_WAIT(0);
        }
        __syncthreads();
        const float* Ab = As + (t&1) * 128*36;
        const float* Bb = Bs + (t&1) * 128*36;
#pragma unroll
        for (int kk = 0; kk < 32; kk += 8) {
            wmma::fragment<wmma::matrix_a, 16, 16, 8, wmma::precision::tf32, wmma::row_major> af[4];
            wmma::fragment<wmma::matrix_b, 16, 16, 8, wmma::precision::tf32, wmma::col_major> bf[2];
#pragma unroll
            for (int i = 0; i < 4; i++)
                wmma::load_matrix_sync(af[i], &Ab[(wm*64 + i*16)*36 + kk], 36);
#pragma unroll
            for (int j = 0; j < 2; j++)
                wmma::load_matrix_sync(bf[j], &Bb[(wn*32 + j*16)*36 + kk], 36);
#pragma unroll
            for (int i = 0; i < 4; i++)
#pragma unroll
                for (int j = 0; j < 2; j++)
                    wmma::mma_sync(acc[i][j], af[i], bf[j], acc[i][j]);
        }
        __syncthreads();
    }
#pragma unroll
    for (int i = 0; i < 4; i++)
#pragma unroll
        for (int j = 0; j < 2; j++)
            wmma::store_matrix_sync(&Cg[(size_t)(wm*64 + i*16) * ldc + wn*32 + j*16],
                                    acc[i][j], ldc, wmma::mem_row_major);
}

// fused QKV projection: grid (20, 32)
__global__ __launch_bounds__(256, 2) void gemm_qkv()
{
    const int nt = blockIdx.x, mt = blockIdx.y;
    const float* B; float* Cb; int ldc;
    if (nt < 16)      { B = g_qwt + (size_t)nt*128*HID_;      Cb = g_q + (size_t)mt*128*(NH_*HD_)  + nt*128;      ldc = NH_*HD_; }
    else if (nt < 18) { B = g_kwt + (size_t)(nt-16)*128*HID_; Cb = g_k + (size_t)mt*128*(NKV_*HD_) + (nt-16)*128; ldc = NKV_*HD_; }
    else              { B = g_vwt + (size_t)(nt-18)*128*HID_; Cb = g_v + (size_t)mt*128*(NKV_*HD_) + (nt-18)*128; ldc = NKV_*HD_; }
    gemm_core(g_hst + (size_t)mt*128*HID_, B, Cb, HID_, ldc);
}

// output projection: grid (16, 32)
__global__ __launch_bounds__(256, 2) void gemm_o(float* __restrict__ out)
{
    const int nt = blockIdx.x, mt = blockIdx.y;
    gemm_core(g_attn + (size_t)mt*128*(NH_*HD_),
              g_owt  + (size_t)nt*128*(NH_*HD_),
              out    + (size_t)mt*128*HID_ + nt*128,
              NH_*HD_, HID_);
}

// ---------------- RoPE in-place with fused bias add; rounds output to tf32 ----------------
__global__ void rope_bias_kernel(float* __restrict__ x, const float* __restrict__ bias,
                                 int nheads, int total)
{
    int idx = blockIdx.x * blockDim.x + threadIdx.x;
    if (idx >= total) return;
    int j = idx & 63;
    int h = (idx >> 6) % nheads;
    int s = (idx >> 6) / nheads;
    float fr = (float)s * g_invfreq[j];
    float c, sn;
    sincosf(fr, &sn, &c);
    float* p = x + (size_t)s * nheads * HD_ + h * HD_;
    float x1 = p[j]      + bias[h*HD_ + j];
    float x2 = p[j + 64] + bias[h*HD_ + j + 64];
    p[j]      = t32(x1 * c - x2 * sn);
    p[j + 64] = t32(x2 * c + x1 * sn);
}

// ---------------- V bias add (rounds output) ----------------
__global__ void bias_v_kernel(float* __restrict__ v, const float* __restrict__ b)
{
    int i = blockIdx.x * blockDim.x + threadIdx.x;
    v[i] = t32(v[i] + b[i & (NKV_*HD_ - 1)]);
}

// ---------------- attention pass 1 v3: 128-col K tiles, half-range Q reg cache ----------------
// smem: Qs[128][132] + K ring 2 x [128][132]; S tile reuses the consumed K buffer.
#define P1_SMEM (3 * 128 * 132 * 4)   // 202752
__global__ __launch_bounds__(256, 1) void attn_pass1_t()
{
    extern __shared__ float sm[];
    float* Qs = sm;                      // [128][132], persistent
    float* Ks = sm + 128*132;            // 2 x [128][132]
    const int qb   = gridDim.x - 1 - blockIdx.x;
    const int h    = blockIdx.y;
    const int kv   = h >> 3;
    const int row0 = qb * 128;
    const int tid  = threadIdx.x;
    const int warp = tid >> 5;
    const int wm = warp >> 1;            // 0..3 -> 32 rows
    const int wn = warp & 1;             // 0..1 -> 64 cols
    const float scale = 0.08838834764831845f;
    const int ncols = (qb + 1) * 128;
    const size_t sbase = (size_t)h * STOT + (size_t)16384 * ((size_t)qb * (qb + 1) / 2);
    const int nj = qb + 1;

    // preload K tile 0 (128 seq rows x 128 d)
#pragma unroll
    for (int it = 0; it < 16; it++) {
        int fid = tid + it * 256;
        int r = fid >> 5, c = (fid & 31) * 4;
        cp16(&Ks[r*132 + c], &g_k[(size_t)r * (NKV_*HD_) + kv*HD_ + c]);
    }
    CP_COMMIT();

    // stage Q (persistent)
#pragma unroll
    for (int it = 0; it < 16; it++) {
        int fid = tid + it * 256;
        int r = fid >> 5, c = (fid & 31) * 4;
        *(float4*)&Qs[r*132 + c] =
            *(const float4*)&g_q[(size_t)(row0 + r) * (NH_*HD_) + h*HD_ + c];
    }
    __syncthreads();

    // register-cache Q a-fragments for d-steps 0..7 (64 regs; no spill)
    wmma::fragment<wmma::matrix_a, 16, 16, 8, wmma::precision::tf32, wmma::row_major> afc[2][8];
#pragma unroll
    for (int i = 0; i < 2; i++)
#pragma unroll
        for (int d = 0; d < 8; d++)
            wmma::load_matrix_sync(afc[i][d], &Qs[(wm*32 + i*16)*132 + d*8], 132);

    const int rrow = tid >> 1;
    const int half = tid & 1;
    const int qi   = row0 + rrow;
    float m_run = -1e30f, l_run = 0.f;

    for (int jb = 0; jb < nj; jb++) {
        // prefetch K(jb+1) into buffer (jb+1)&1 (free: its S tile was consumed last iter)
        if (jb + 1 < nj) {
            float* dst = Ks + ((jb+1)&1) * 128*132;
            const int r0n = (jb+1) * 128;
#pragma unroll
            for (int it = 0; it < 16; it++) {
                int fid = tid + it * 256;
                int r = fid >> 5, c = (fid & 31) * 4;
                cp16(&dst[r*132 + c], &g_k[(size_t)(r0n + r) * (NKV_*HD_) + kv*HD_ + c]);
            }
            CP_COMMIT();
            CP_WAIT(1);
        } else {
            CP_WAIT(0);
        }
        __syncthreads();               // K(jb) visible
        float* Kb = Ks + (jb&1) * 128*132;

        wmma::fragment<wmma::accumulator, 16, 16, 8, float> acc[2][4];
#pragma unroll
        for (int i = 0; i < 2; i++)
#pragma unroll
            for (int j = 0; j < 4; j++) wmma::fill_fragment(acc[i][j], 0.0f);

        // d 0..7: cached a-frags, only b loads
#pragma unroll
        for (int d = 0; d < 8; d++) {
            wmma::fragment<wmma::matrix_b, 16, 16, 8, wmma::precision::tf32, wmma::col_major> bf[4];
#pragma unroll
            for (int j = 0; j < 4; j++)
                wmma::load_matrix_sync(bf[j], &Kb[(wn*64 + j*16)*132 + d*8], 132);
#pragma unroll
            for (int i = 0; i < 2; i++)
#pragma unroll
                for (int j = 0; j < 4; j++)
                    wmma::mma_sync(acc[i][j], afc[i][d], bf[j], acc[i][j]);
        }
        // d 8..15: a from smem + b loads
#pragma unroll
        for (int d = 8; d < 16; d++) {
            wmma::fragment<wmma::matrix_a, 16, 16, 8, wmma::precision::tf32, wmma::row_major> af[2];
            wmma::fragment<wmma::matrix_b, 16, 16, 8, wmma::precision::tf32, wmma::col_major> bf[4];
#pragma unroll
            for (int i = 0; i < 2; i++)
                wmma::load_matrix_sync(af[i], &Qs[(wm*32 + i*16)*132 + d*8], 132);
#pragma unroll
            for (int j = 0; j < 4; j++)
                wmma::load_matrix_sync(bf[j], &Kb[(wn*64 + j*16)*132 + d*8], 132);
#pragma unroll
            for (int i = 0; i < 2; i++)
#pragma unroll
                for (int j = 0; j < 4; j++)
                    wmma::mma_sync(acc[i][j], af[i], bf[j], acc[i][j]);
        }
        __syncthreads();               // all warps done reading K(jb)

        // store S tile into the consumed K buffer
#pragma unroll
        for (int i = 0; i < 2; i++)
#pragma unroll
            for (int j = 0; j < 4; j++)
                wmma::store_matrix_sync(&Kb[(wm*32 + i*16)*132 + wn*64 + j*16],
                                        acc[i][j], 132, wmma::mem_row_major);
        __syncthreads();

        // online (m, l) stats over 128 cols; row owned by thread pair
        {
            const float* srow = &Kb[rrow*132 + half*64];
            const int cb = jb*128 + half*64;
            float lmax = -1e30f;
#pragma unroll
            for (int c = 0; c < 64; c++) {
                float s = (cb + c <= qi) ? srow[c]*scale : -1e30f;
                lmax = fmaxf(lmax, s);
            }
            lmax = fmaxf(lmax, __shfl_xor_sync(0xffffffffu, lmax, 1));
            float nm = fmaxf(m_run, lmax);
            float ps = 0.f;
#pragma unroll
            for (int c = 0; c < 64; c++) {
                float s = (cb + c <= qi) ? srow[c]*scale : -1e30f;
                ps += __expf(s - nm);
            }
            ps += __shfl_xor_sync(0xffffffffu, ps, 1);
            l_run = l_run * __expf(m_run - nm) + ps;
            m_run = nm;
        }

        // write raw S tile (128 x 128) to gmem for pass2
        {
            float* dst = g_s + sbase + (size_t)jb * 128;
#pragma unroll
            for (int it = 0; it < 16; it++) {
                int fid = tid + it * 256;
                int r = fid >> 5, c = (fid & 31) * 4;
                *(float4*)&dst[(size_t)r * ncols + c] = *(const float4*)&Kb[r*132 + c];
            }
        }
        __syncthreads();               // S consumed before next-iter prefetch overwrites
    }
    if (half == 0) {
        g_m[h*SQ + qi] = m_run;
        g_l[h*SQ + qi] = l_run;
    }
}

// ---------------- zero colsum ----------------
__global__ void zero_colsum()
{
    g_colsum[blockIdx.x * blockDim.x + threadIdx.x] = 0.f;
}

// ---------------- attention pass 2: stream S + V, exact probs -> O + column sums ----------------
#define P2_SMEM ((2*128*68 + 2*64*132 + 256) * 4)
__global__ __launch_bounds__(256, 1) void attn_pass2_t()
{
    extern __shared__ float sm[];
    float* Ss = sm;                  // 2 x [128][68]
    float* Vs = Ss + 2*128*68;       // 2 x [64][132]
    float* Cs = Vs + 2*64*132;       // [4][64]
    const int qb   = gridDim.x - 1 - blockIdx.x;
    const int h    = blockIdx.y;
    const int kv   = h >> 3;
    const int row0 = qb * 128;
    const int tid  = threadIdx.x;
    const int warp = tid >> 5;
    const int wm = warp >> 1;        // 0..3
    const int wn = warp & 1;         // 0..1
    const float scale = 0.08838834764831845f;
    const int nj = 2 * qb + 2;
    const int ncols = (qb + 1) * 128;
    const size_t sbase = (size_t)h * STOT + (size_t)16384 * ((size_t)qb * (qb + 1) / 2);

    const int rrow = tid >> 1;
    const int half = tid & 1;
    const int qi   = row0 + rrow;
    const float mr = g_m[h*SQ + qi];
    const float il = 1.0f / g_l[h*SQ + qi];

    wmma::fragment<wmma::accumulator, 16, 16, 8, float> acc_o[2][4];
#pragma unroll
    for (int i = 0; i < 2; i++)
#pragma unroll
        for (int j = 0; j < 4; j++) wmma::fill_fragment(acc_o[i][j], 0.0f);

    // tile loader: S (128x64 from packed gmem) + V (64x128), one commit group
    auto load_tiles = [&](int jb) {
        float* Sd = Ss + (jb&1) * 128*68;
        float* Vd = Vs + (jb&1) * 64*132;
        const float* Sg = g_s + sbase + (size_t)jb * 64;
#pragma unroll
        for (int it = 0; it < 8; it++) {
            int fid = tid + it * 256;
            int r = fid >> 4, c = (fid & 15) * 4;
            cp16(&Sd[r*68 + c], &Sg[(size_t)r * ncols + c]);
        }
#pragma unroll
        for (int it = 0; it < 8; it++) {
            int fid = tid + it * 256;
            int r = fid >> 5, c = (fid & 31) * 4;
            cp16(&Vd[r*132 + c], &g_v[(size_t)(jb*64 + r) * (NKV_*HD_) + kv*HD_ + c]);
        }
        CP_COMMIT();
    };

    load_tiles(0);

    for (int jb = 0; jb < nj; jb++) {
        const int col0 = jb * 64;
        if (jb + 1 < nj) { load_tiles(jb + 1); CP_WAIT(1); }
        else             { CP_WAIT(0); }
        __syncthreads();
        float* Sb = Ss + (jb&1) * 128*68;
        const float* Vb = Vs + (jb&1) * 64*132;

        // exact normalized probs in place (tf32-rounded for PV)
        {
            float* srow = &Sb[rrow*68 + half*32];
            const int cb = col0 + half*32;
#pragma unroll
            for (int c = 0; c < 32; c++) {
                float s = (cb + c <= qi) ? srow[c]*scale : -1e30f;
                srow[c] = t32(__expf(s - mr) * il);
            }
        }
        __syncthreads();

        // column-sum partials
        {
            int col = tid & 63, seg = tid >> 6;
            float cs = 0.f;
#pragma unroll 8
            for (int r = 0; r < 32; r++)
                cs += Sb[(seg*32 + r)*68 + col];
            Cs[seg*64 + col] = cs;
        }
        __syncthreads();
        if (tid < 64)
            atomicAdd(&g_colsum[h*SQ + col0 + tid],
                      Cs[tid] + Cs[64+tid] + Cs[128+tid] + Cs[192+tid]);

        // O += P @ V
#pragma unroll
        for (int k0 = 0; k0 < 64; k0 += 8) {
            wmma::fragment<wmma::matrix_a, 16, 16, 8, wmma::precision::tf32, wmma::row_major> pf[2];
            wmma::fragment<wmma::matrix_b, 16, 16, 8, wmma::precision::tf32, wmma::row_major> vf[4];
#pragma unroll
            for (int i = 0; i < 2; i++)
                wmma::load_matrix_sync(pf[i], &Sb[(wm*32 + i*16)*68 + k0], 68);
#pragma unroll
            for (int j = 0; j < 4; j++)
                wmma::load_matrix_sync(vf[j], &Vb[k0*132 + wn*64 + j*16], 132);
#pragma unroll
            for (int i = 0; i < 2; i++)
#pragma unroll
                for (int j = 0; j < 4; j++)
                    wmma::mma_sync(acc_o[i][j], pf[i], vf[j], acc_o[i][j]);
        }
        __syncthreads();   // before buffers of this parity are overwritten
    }

    // round O (tensor input of O-proj), then store
#pragma unroll
    for (int i = 0; i < 2; i++)
#pragma unroll
        for (int j = 0; j < 4; j++) {
#pragma unroll
            for (int e = 0; e < acc_o[i][j].num_elements; e++)
                acc_o[i][j].x[e] = t32(acc_o[i][j].x[e]);
            wmma::store_matrix_sync(
                &g_attn[(size_t)(row0 + wm*32 + i*16) * (NH_*HD_) + h*HD_ + wn*64 + j*16],
                acc_o[i][j], NH_*HD_, wmma::mem_row_major);
        }
}

// ---------------- finalize accumulated_scores ----------------
__global__ void finalize_acc(float* __restrict__ out_acc)
{
    int idx = blockIdx.x * blockDim.x + threadIdx.x;  // 0..8191
    int kvh = idx >> 12;
    int col = idx & 4095;
    float s = 0.f;
#pragma unroll
    for (int g = 0; g < GRP_; g++)
        s += g_colsum[(kvh*GRP_ + g)*SQ + col];
    out_acc[idx] = s * 0.125f;
}

// ---------------- launch ----------------
extern "C" void kernel_launch(void* const* d_in, const int* in_sizes, int n_in,
                              void* d_out, int out_size)
{
    const float* hs = (const float*)d_in[0];
    const float* qw = (const float*)d_in[1];
    const float* qbias = (const float*)d_in[2];
    const float* kw = (const float*)d_in[3];
    const float* kbias = (const float*)d_in[4];
    const float* vw = (const float*)d_in[5];
    const float* vbias = (const float*)d_in[6];
    const float* ow = (const float*)d_in[7];
    float* out = (float*)d_out;

    float *qp, *kp, *vp;
    float *hst, *qwt, *kwt, *vwt, *owt;
    cudaGetSymbolAddress((void**)&qp, g_q);
    cudaGetSymbolAddress((void**)&kp, g_k);
    cudaGetSymbolAddress((void**)&vp, g_v);
    cudaGetSymbolAddress((void**)&hst, g_hst);
    cudaGetSymbolAddress((void**)&qwt, g_qwt);
    cudaGetSymbolAddress((void**)&kwt, g_kwt);
    cudaGetSymbolAddress((void**)&vwt, g_vwt);
    cudaGetSymbolAddress((void**)&owt, g_owt);

    cudaFuncSetAttribute(gemm_qkv, cudaFuncAttributeMaxDynamicSharedMemorySize, GEMM_SMEM_BYTES);
    cudaFuncSetAttribute(gemm_o,   cudaFuncAttributeMaxDynamicSharedMemorySize, GEMM_SMEM_BYTES);
    cudaFuncSetAttribute(attn_pass1_t, cudaFuncAttributeMaxDynamicSharedMemorySize, P1_SMEM);
    cudaFuncSetAttribute(attn_pass2_t, cudaFuncAttributeMaxDynamicSharedMemorySize, P2_SMEM);

    compute_invfreq<<<1, 64>>>();

    // pre-round all tensor operands once
    copy_round4<<<(SQ*HID_/4 + 255)/256, 256>>>(hst, hs, SQ*HID_/4);
    copy_round4<<<(NH_*HD_*HID_/4 + 255)/256, 256>>>(qwt, qw, NH_*HD_*HID_/4);
    copy_round4<<<(NKV_*HD_*HID_/4 + 255)/256, 256>>>(kwt, kw, NKV_*HD_*HID_/4);
    copy_round4<<<(NKV_*HD_*HID_/4 + 255)/256, 256>>>(vwt, vw, NKV_*HD_*HID_/4);
    copy_round4<<<(HID_*NH_*HD_/4 + 255)/256, 256>>>(owt, ow, HID_*NH_*HD_/4);

    // fused QKV projection
    gemm_qkv<<<dim3(20, 32), 256, GEMM_SMEM_BYTES>>>();

    rope_bias_kernel<<<(SQ*NH_*64)/256,  256>>>(qp, qbias, NH_,  SQ*NH_*64);
    rope_bias_kernel<<<(SQ*NKV_*64)/256, 256>>>(kp, kbias, NKV_, SQ*NKV_*64);
    bias_v_kernel<<<(SQ*NKV_*HD_)/256, 256>>>(vp, vbias);

    attn_pass1_t<<<dim3(32, 16), 256, P1_SMEM>>>();
    zero_colsum<<<(NH_*SQ)/256, 256>>>();
    attn_pass2_t<<<dim3(32, 16), 256, P2_SMEM>>>();

    gemm_o<<<dim3(16, 32), 256, GEMM_SMEM_BYTES>>>(out);
    finalize_acc<<<(NKV_*SQ)/256, 256>>>(out + (out_size - NKV_*SQ));
}